// round 1
// baseline (speedup 1.0000x reference)
#include <cuda_runtime.h>
#include <cstdint>

// Farthest Point Sampling, B=16, N=65536, S=2048, out = coords of selected (B,S,3) f32.
// Cluster of 8 CTAs per batch; coords SoA in SMEM; closest[] in registers;
// hierarchical argmax with first-index tie-break; DSMEM cluster reduction.

#define NBATCH   16
#define NPTS     65536
#define NSAMP    2048
#define CLUSTER  8
#define NPC      (NPTS / CLUSTER)     // 8192 points per CTA
#define THREADS  512
#define NWARPS   (THREADS / 32)       // 16
#define PPT      (NPC / THREADS)      // 16 points per thread
#define GROUPS   (PPT / 4)            // 4 float4 groups

struct __align__(16) Smem {
    float x[NPC];
    float y[NPC];
    float z[NPC];
    float wval[NWARPS];
    int   widx[NWARPS];
    float sval[2];     // double-buffered cluster slot (own CTA's best value)
    int   sidx[2];     // global index of own CTA's best
    float bc[4];       // broadcast: selected point coords
};

__device__ __forceinline__ uint32_t smem_u32(const void* p) {
    return (uint32_t)__cvta_generic_to_shared(p);
}

__global__ void __cluster_dims__(CLUSTER, 1, 1) __launch_bounds__(THREADS, 1)
fps_kernel(const float* __restrict__ pc, float* __restrict__ out)
{
    extern __shared__ Smem sm[];
    Smem& s = *sm;

    const int tid  = threadIdx.x;
    const int lane = tid & 31;
    const int warp = tid >> 5;
    const int rank = blockIdx.x & (CLUSTER - 1);
    const int b    = blockIdx.x >> 3;

    const float* __restrict__ base = pc + (size_t)b * NPTS * 3;

    // ---- prologue: stage this CTA's coords into SMEM as SoA ----
    for (int i = tid; i < NPC; i += THREADS) {
        int gi = rank * NPC + i;
        s.x[i] = base[gi * 3 + 0];
        s.y[i] = base[gi * 3 + 1];
        s.z[i] = base[gi * 3 + 2];
    }

    float closest[PPT];
    #pragma unroll
    for (int i = 0; i < PPT; i++) closest[i] = __int_as_float(0x7f800000);  // +inf

    // initial selection: global point 0 of this batch
    float sx = base[0];
    float sy = base[1];
    float sz = base[2];

    __syncthreads();

    for (int it = 0; it < NSAMP; ++it) {
        const int p = it & 1;

        // ---- distance update + min + thread-local argmax (ascending index, strict >) ----
        float best = -1.0f;
        int   bidx = 0x7fffffff;
        #pragma unroll
        for (int g = 0; g < GROUPS; ++g) {
            const int bi = g * (THREADS * 4) + tid * 4;
            float4 xv = *reinterpret_cast<const float4*>(&s.x[bi]);
            float4 yv = *reinterpret_cast<const float4*>(&s.y[bi]);
            float4 zv = *reinterpret_cast<const float4*>(&s.z[bi]);
            float xs[4] = {xv.x, xv.y, xv.z, xv.w};
            float ys[4] = {yv.x, yv.y, yv.z, yv.w};
            float zs[4] = {zv.x, zv.y, zv.z, zv.w};
            #pragma unroll
            for (int j = 0; j < 4; ++j) {
                // match XLA: sub, square (no FMA), left-assoc sum
                float dx = __fadd_rn(sx, -xs[j]);
                float dy = __fadd_rn(sy, -ys[j]);
                float dz = __fadd_rn(sz, -zs[j]);
                float d  = __fadd_rn(__fadd_rn(__fmul_rn(dx, dx), __fmul_rn(dy, dy)),
                                     __fmul_rn(dz, dz));
                float c = closest[g * 4 + j];
                c = fminf(c, d);
                closest[g * 4 + j] = c;
                if (c > best) { best = c; bidx = bi + j; }
            }
        }

        // ---- warp argmax (tie -> lowest index) ----
        #pragma unroll
        for (int off = 16; off > 0; off >>= 1) {
            float ov = __shfl_down_sync(0xffffffffu, best, off);
            int   oi = __shfl_down_sync(0xffffffffu, bidx, off);
            if (ov > best || (ov == best && oi < bidx)) { best = ov; bidx = oi; }
        }
        if (lane == 0) { s.wval[warp] = best; s.widx[warp] = bidx; }
        __syncthreads();

        // ---- CTA argmax over 16 warp results (warp 0) ----
        if (warp == 0) {
            float v  = (lane < NWARPS) ? s.wval[lane] : -1.0f;
            int   ix = (lane < NWARPS) ? s.widx[lane] : 0x7fffffff;
            #pragma unroll
            for (int off = 8; off > 0; off >>= 1) {
                float ov = __shfl_down_sync(0xffffffffu, v, off);
                int   oi = __shfl_down_sync(0xffffffffu, ix, off);
                if (ov > v || (ov == v && oi < ix)) { v = ov; ix = oi; }
            }
            if (lane == 0) {
                s.sval[p] = v;
                s.sidx[p] = rank * NPC + ix;   // global point index within batch
            }
        }

        // ---- cluster barrier: publish slots ----
        asm volatile("barrier.cluster.arrive.aligned;\n" ::: "memory");
        asm volatile("barrier.cluster.wait.aligned;\n" ::: "memory");

        // ---- cluster argmax over 8 CTA results (warp 0, lanes 0..7 read DSMEM) ----
        if (warp == 0) {
            float v  = -1.0f;
            int   ix = 0x7fffffff;
            if (lane < CLUSTER) {
                uint32_t a_val = smem_u32(&s.sval[p]);
                uint32_t a_idx = smem_u32(&s.sidx[p]);
                uint32_t rv, ri;
                asm volatile("mapa.shared::cluster.u32 %0, %1, %2;"
                             : "=r"(rv) : "r"(a_val), "r"(lane));
                asm volatile("mapa.shared::cluster.u32 %0, %1, %2;"
                             : "=r"(ri) : "r"(a_idx), "r"(lane));
                asm volatile("ld.shared::cluster.f32 %0, [%1];" : "=f"(v)  : "r"(rv));
                asm volatile("ld.shared::cluster.s32 %0, [%1];" : "=r"(ix) : "r"(ri));
            }
            #pragma unroll
            for (int off = 4; off > 0; off >>= 1) {
                float ov = __shfl_down_sync(0xffffffffu, v, off);
                int   oi = __shfl_down_sync(0xffffffffu, ix, off);
                if (ov > v || (ov == v && oi < ix)) { v = ov; ix = oi; }
            }
            if (lane == 0) {
                // fetch selected coords from global (L2-hit; bit-identical to input)
                const float* g = base + (size_t)ix * 3;
                float cx = g[0], cy = g[1], cz = g[2];
                if (rank == 0) {
                    float* o = out + ((size_t)b * NSAMP + it) * 3;
                    o[0] = cx; o[1] = cy; o[2] = cz;
                }
                s.bc[0] = cx; s.bc[1] = cy; s.bc[2] = cz;
            }
        }
        __syncthreads();
        sx = s.bc[0]; sy = s.bc[1]; sz = s.bc[2];
    }
}

extern "C" void kernel_launch(void* const* d_in, const int* in_sizes, int n_in,
                              void* d_out, int out_size)
{
    (void)in_sizes; (void)n_in; (void)out_size;
    const float* pc  = (const float*)d_in[0];   // point_coord (16, 65536, 3) f32
    float*       out = (float*)d_out;           // (16, 2048, 3) f32

    static bool attr_set = false;
    if (!attr_set) {
        cudaFuncSetAttribute(fps_kernel,
                             cudaFuncAttributeMaxDynamicSharedMemorySize,
                             (int)sizeof(Smem));
        attr_set = true;
    }
    fps_kernel<<<NBATCH * CLUSTER, THREADS, sizeof(Smem)>>>(pc, out);
}